// round 1
// baseline (speedup 1.0000x reference)
#include <cuda_runtime.h>

// PPISP: per-point ISP pipeline.
// out[b] = b_crf * sigmoid((pow(max(colorMat @ (vignette * exp2(expo) * rgb), 1e-6), a) - d)/c)
//
// Input order (metadata):
//  0: exposure_params   float32 [F=1000]
//  1: vignetting_params float32 [C=4, 3, 5]
//  2: color_params      float32 [F, 8]
//  3: crf_params        float32 [C, 3, 4]
//  4: rgb               float32 [B, 3]
//  5: pixel_coords      float32 [B, 2]
//  6: camera_idcs       int32   [B]
//  7: frame_idcs        int32   [B]
//  8: resolution_w      int32   [1]
//  9: resolution_h      int32   [1]
// output: float32 [B, 3]

__device__ __forceinline__ float softplus_f(float x) {
    // matches jax.nn.softplus for the small |x| in this problem
    return log1pf(expf(x));
}

__device__ __forceinline__ void process_point(
    float r, float g, float b,
    float px, float py,
    int cam, int frm,
    const float* __restrict__ expo,
    const float* __restrict__ vig,
    const float* __restrict__ colp,
    const float* __restrict__ crf,
    float invW2, float invH2,
    float* o /* 3 outputs */)
{
    // exposure
    float e = exp2f(__ldg(expo + frm));
    float x0 = r * e, x1 = g * e, x2 = b * e;

    // vignetting
    float u = px * invW2 - 1.0f;
    float v = py * invH2 - 1.0f;
    const float* vp = vig + cam * 15;
    float xs[3] = {x0, x1, x2};
#pragma unroll
    for (int j = 0; j < 3; j++) {
        float du = u - __ldg(vp + 5 * j + 0);
        float dv = v - __ldg(vp + 5 * j + 1);
        float r2 = du * du + dv * dv;
        float p2 = __ldg(vp + 5 * j + 2);
        float p3 = __ldg(vp + 5 * j + 3);
        float p4 = __ldg(vp + 5 * j + 4);
        float gph = fmaf(r2, fmaf(r2, fmaf(r2, p4, p3), p2), 1.0f);
        xs[j] *= gph;
    }
    x0 = xs[0]; x1 = xs[1]; x2 = xs[2];

    // color: white balance + mixing matrix
    const float* cp = colp + frm * 8;
    float cp0 = __ldg(cp + 0), cp1 = __ldg(cp + 1);
    float o0 = __ldg(cp + 2), o1 = __ldg(cp + 3);
    float o2 = __ldg(cp + 4), o3 = __ldg(cp + 5);
    float o4 = __ldg(cp + 6), o5 = __ldg(cp + 7);
    x0 *= expf(cp0);
    x2 *= expf(cp1);

    float y[3];
    y[0] = (1.0f - o0 - o1) * x0 + o0 * x1 + o1 * x2;
    y[1] = o2 * x0 + (1.0f - o2 - o3) * x1 + o3 * x2;
    y[2] = o4 * x0 + o5 * x1 + (1.0f - o4 - o5) * x2;

    // CRF
    const float* kp = crf + cam * 12;
#pragma unroll
    for (int j = 0; j < 3; j++) {
        float a  = softplus_f(__ldg(kp + 4 * j + 0)) + 0.3f;
        float bb = softplus_f(__ldg(kp + 4 * j + 1)) + 0.3f;
        float cc = softplus_f(__ldg(kp + 4 * j + 2)) + 0.1f;
        float d  = __ldg(kp + 4 * j + 3);
        float xp = exp2f(a * log2f(fmaxf(y[j], 1e-6f)));
        float t  = (xp - d) / cc;
        // sigmoid
        float s  = 1.0f / (1.0f + expf(-t));
        o[j] = bb * s;
    }
}

__global__ void __launch_bounds__(256)
ppisp_kernel(
    const float* __restrict__ expo,
    const float* __restrict__ vig,
    const float* __restrict__ colp,
    const float* __restrict__ crf,
    const float* __restrict__ rgb,
    const float* __restrict__ coords,
    const int*   __restrict__ cam,
    const int*   __restrict__ frm,
    const int*   __restrict__ pW,
    const int*   __restrict__ pH,
    float* __restrict__ out,
    int B)
{
    int t = blockIdx.x * blockDim.x + threadIdx.x;
    int i0 = t * 4;
    if (i0 >= B) return;

    float invW2 = 2.0f / (float)__ldg(pW);
    float invH2 = 2.0f / (float)__ldg(pH);

    if (i0 + 3 < B) {
        // vectorized path: 4 points per thread, all float4/int4 traffic
        const float4* rgb4 = (const float4*)rgb;
        const float4* pc4  = (const float4*)coords;
        float4 ra = rgb4[3 * t + 0];
        float4 rb = rgb4[3 * t + 1];
        float4 rc = rgb4[3 * t + 2];
        float4 pa = pc4[2 * t + 0];
        float4 pb = pc4[2 * t + 1];
        int4 c4 = ((const int4*)cam)[t];
        int4 f4 = ((const int4*)frm)[t];

        float o[12];
        process_point(ra.x, ra.y, ra.z, pa.x, pa.y, c4.x, f4.x,
                      expo, vig, colp, crf, invW2, invH2, o + 0);
        process_point(ra.w, rb.x, rb.y, pa.z, pa.w, c4.y, f4.y,
                      expo, vig, colp, crf, invW2, invH2, o + 3);
        process_point(rb.z, rb.w, rc.x, pb.x, pb.y, c4.z, f4.z,
                      expo, vig, colp, crf, invW2, invH2, o + 6);
        process_point(rc.y, rc.z, rc.w, pb.z, pb.w, c4.w, f4.w,
                      expo, vig, colp, crf, invW2, invH2, o + 9);

        float4* O = (float4*)out;
        O[3 * t + 0] = make_float4(o[0], o[1], o[2],  o[3]);
        O[3 * t + 1] = make_float4(o[4], o[5], o[6],  o[7]);
        O[3 * t + 2] = make_float4(o[8], o[9], o[10], o[11]);
    } else {
        // scalar tail
        for (int i = i0; i < B; i++) {
            float o[3];
            process_point(rgb[3 * i], rgb[3 * i + 1], rgb[3 * i + 2],
                          coords[2 * i], coords[2 * i + 1],
                          cam[i], frm[i],
                          expo, vig, colp, crf, invW2, invH2, o);
            out[3 * i + 0] = o[0];
            out[3 * i + 1] = o[1];
            out[3 * i + 2] = o[2];
        }
    }
}

extern "C" void kernel_launch(void* const* d_in, const int* in_sizes, int n_in,
                              void* d_out, int out_size) {
    const float* expo   = (const float*)d_in[0];
    const float* vig    = (const float*)d_in[1];
    const float* colp   = (const float*)d_in[2];
    const float* crf    = (const float*)d_in[3];
    const float* rgb    = (const float*)d_in[4];
    const float* coords = (const float*)d_in[5];
    const int*   cam    = (const int*)d_in[6];
    const int*   frm    = (const int*)d_in[7];
    const int*   pW     = (const int*)d_in[8];
    const int*   pH     = (const int*)d_in[9];
    float* out = (float*)d_out;

    int B = in_sizes[6];              // camera_idcs element count == B
    int threads = 256;
    int n_threads = (B + 3) / 4;      // 4 points per thread
    int blocks = (n_threads + threads - 1) / threads;

    ppisp_kernel<<<blocks, threads>>>(expo, vig, colp, crf, rgb, coords,
                                      cam, frm, pW, pH, out, B);
}

// round 2
// speedup vs baseline: 1.5266x; 1.5266x over previous
#include <cuda_runtime.h>

// PPISP pipeline, two-kernel form:
//  K1 (precompute, ~1000 threads of work):
//    - per-frame: fold exp2(exposure) and exp(white-balance) into the 3x3
//      color matrix -> M'[9] per frame (stride 16 floats, 64B aligned).
//    - per-(camera,channel): vignetting center/poly + softplus'd CRF params,
//      with sigmoid/scale constants pre-folded:
//        a, hc = 0.5/c, hd = d*hc, hb = 0.5*b
//      so per point: out = hb * tanh(xp*hc - hd) + hb  == b*sigmoid((xp-d)/c)
//  K2 (main, 4 points/thread, all streaming as float4/int4):
//    per point: 3 vector frame gathers + 7 vector camera gathers (4 distinct
//    addrs/warp -> L1 broadcast), polynomial vignette, 3x3 matvec, and
//    CRF = lg2.approx + ex2.approx + tanh.approx (3 MUFU per channel).
//
// Input order (metadata):
//  0 exposure[F] 1 vignetting[C,3,5] 2 color[F,8] 3 crf[C,3,4]
//  4 rgb[B,3] 5 pixel_coords[B,2] 6 camera_idcs[B] 7 frame_idcs[B]
//  8 W 9 H ; output float32 [B,3]

#define MAX_F 8192
#define MAX_C 16

__device__ float4 g_frame[MAX_F * 4];   // 16 floats per frame, first 9 used (M')
__device__ float4 g_camA[MAX_C * 3];    // {v0, v1, p2, p3}
__device__ float4 g_camB[MAX_C * 3];    // {p4, a, hc, hd}
__device__ float4 g_camHb[MAX_C];       // {hb0, hb1, hb2, 0}

__global__ void ppisp_precompute(const float* __restrict__ expo,
                                 const float* __restrict__ vig,
                                 const float* __restrict__ colp,
                                 const float* __restrict__ crf,
                                 int F, int C)
{
    int t = blockIdx.x * blockDim.x + threadIdx.x;
    if (t < F) {
        float e  = exp2f(expo[t]);
        const float* cp = colp + t * 8;
        float s0 = e * expf(cp[0]);
        float s1 = e;
        float s2 = e * expf(cp[1]);
        float o0 = cp[2], o1 = cp[3], o2 = cp[4];
        float o3 = cp[5], o4 = cp[6], o5 = cp[7];
        float* dst = (float*)(g_frame + t * 4);
        dst[0] = (1.0f - o0 - o1) * s0;
        dst[1] = o0 * s1;
        dst[2] = o1 * s2;
        dst[3] = o2 * s0;
        dst[4] = (1.0f - o2 - o3) * s1;
        dst[5] = o3 * s2;
        dst[6] = o4 * s0;
        dst[7] = o5 * s1;
        dst[8] = (1.0f - o4 - o5) * s2;
    }
    if (blockIdx.x == 0 && (int)threadIdx.x < C * 3) {
        int c = threadIdx.x / 3;
        int j = threadIdx.x % 3;
        const float* vp = vig + c * 15 + j * 5;
        const float* kp = crf + c * 12 + j * 4;
        float a  = log1pf(expf(kp[0])) + 0.3f;   // softplus, accurate
        float b  = log1pf(expf(kp[1])) + 0.3f;
        float cc = log1pf(expf(kp[2])) + 0.1f;
        float d  = kp[3];
        float hc = 0.5f / cc;
        g_camA[c * 3 + j] = make_float4(vp[0], vp[1], vp[2], vp[3]);
        g_camB[c * 3 + j] = make_float4(vp[4], a, hc, d * hc);
        ((float*)(g_camHb + c))[j] = 0.5f * b;
    }
}

__device__ __forceinline__ float fast_lg2(float x) {
    float y; asm("lg2.approx.f32 %0, %1;" : "=f"(y) : "f"(x)); return y;
}
__device__ __forceinline__ float fast_ex2(float x) {
    float y; asm("ex2.approx.f32 %0, %1;" : "=f"(y) : "f"(x)); return y;
}
__device__ __forceinline__ float fast_tanh(float x) {
    float y; asm("tanh.approx.f32 %0, %1;" : "=f"(y) : "f"(x)); return y;
}

__device__ __forceinline__ void process_point(
    float r, float g, float b, float px, float py, int c, int f,
    float invW2, float invH2, float* __restrict__ o)
{
    // gathered frame matrix (random index, 3 loads, <=2 sectors per lane)
    const float4* fr = g_frame + f * 4;
    float4 q0 = __ldg(fr + 0);                  // m00 m01 m02 m10
    float4 q1 = __ldg(fr + 1);                  // m11 m12 m20 m21
    float  m8 = __ldg((const float*)fr + 8);    // m22

    float u = fmaf(px, invW2, -1.0f);
    float v = fmaf(py, invH2, -1.0f);

    float rgbv[3] = {r, g, b};
    float t[3], aj[3], hcj[3], hdj[3];
#pragma unroll
    for (int j = 0; j < 3; j++) {
        float4 A = __ldg(g_camA + c * 3 + j);
        float4 B = __ldg(g_camB + c * 3 + j);
        float du = u - A.x;
        float dv = v - A.y;
        float r2 = fmaf(du, du, dv * dv);
        float gn = fmaf(r2, fmaf(r2, fmaf(r2, B.x, A.w), A.z), 1.0f);
        t[j] = rgbv[j] * gn;
        aj[j] = B.y; hcj[j] = B.z; hdj[j] = B.w;
    }

    float y[3];
    y[0] = fmaf(q0.x, t[0], fmaf(q0.y, t[1], q0.z * t[2]));
    y[1] = fmaf(q0.w, t[0], fmaf(q1.x, t[1], q1.y * t[2]));
    y[2] = fmaf(q1.z, t[0], fmaf(q1.w, t[1], m8   * t[2]));

    float4 HB = __ldg(g_camHb + c);
    float hb[3] = {HB.x, HB.y, HB.z};
#pragma unroll
    for (int j = 0; j < 3; j++) {
        float xp  = fast_ex2(aj[j] * fast_lg2(fmaxf(y[j], 1e-6f)));
        float arg = fmaf(xp, hcj[j], -hdj[j]);      // (xp - d) * (0.5/c)
        float th  = fast_tanh(arg);
        o[j] = fmaf(hb[j], th, hb[j]);              // b * sigmoid((xp-d)/c)
    }
}

__global__ void __launch_bounds__(256)
ppisp_main(const float* __restrict__ rgb,
           const float* __restrict__ coords,
           const int*   __restrict__ cam,
           const int*   __restrict__ frm,
           const int*   __restrict__ pW,
           const int*   __restrict__ pH,
           float* __restrict__ out,
           int B)
{
    int t = blockIdx.x * blockDim.x + threadIdx.x;
    int i0 = t * 4;
    if (i0 >= B) return;

    float invW2 = 2.0f / (float)__ldg(pW);
    float invH2 = 2.0f / (float)__ldg(pH);

    if (i0 + 3 < B) {
        const float4* rgb4 = (const float4*)rgb;
        const float4* pc4  = (const float4*)coords;
        float4 ra = rgb4[3 * t + 0];
        float4 rb = rgb4[3 * t + 1];
        float4 rc = rgb4[3 * t + 2];
        float4 pa = pc4[2 * t + 0];
        float4 pb = pc4[2 * t + 1];
        int4 c4 = ((const int4*)cam)[t];
        int4 f4 = ((const int4*)frm)[t];

        float o[12];
        process_point(ra.x, ra.y, ra.z, pa.x, pa.y, c4.x, f4.x, invW2, invH2, o + 0);
        process_point(ra.w, rb.x, rb.y, pa.z, pa.w, c4.y, f4.y, invW2, invH2, o + 3);
        process_point(rb.z, rb.w, rc.x, pb.x, pb.y, c4.z, f4.z, invW2, invH2, o + 6);
        process_point(rc.y, rc.z, rc.w, pb.z, pb.w, c4.w, f4.w, invW2, invH2, o + 9);

        float4* O = (float4*)out;
        O[3 * t + 0] = make_float4(o[0], o[1], o[2],  o[3]);
        O[3 * t + 1] = make_float4(o[4], o[5], o[6],  o[7]);
        O[3 * t + 2] = make_float4(o[8], o[9], o[10], o[11]);
    } else {
        for (int i = i0; i < B; i++) {
            float o[3];
            process_point(rgb[3 * i], rgb[3 * i + 1], rgb[3 * i + 2],
                          coords[2 * i], coords[2 * i + 1],
                          cam[i], frm[i], invW2, invH2, o);
            out[3 * i + 0] = o[0];
            out[3 * i + 1] = o[1];
            out[3 * i + 2] = o[2];
        }
    }
}

extern "C" void kernel_launch(void* const* d_in, const int* in_sizes, int n_in,
                              void* d_out, int out_size) {
    const float* expo   = (const float*)d_in[0];
    const float* vig    = (const float*)d_in[1];
    const float* colp   = (const float*)d_in[2];
    const float* crf    = (const float*)d_in[3];
    const float* rgb    = (const float*)d_in[4];
    const float* coords = (const float*)d_in[5];
    const int*   cam    = (const int*)d_in[6];
    const int*   frm    = (const int*)d_in[7];
    const int*   pW     = (const int*)d_in[8];
    const int*   pH     = (const int*)d_in[9];
    float* out = (float*)d_out;

    int F = in_sizes[0];
    int C = in_sizes[1] / 15;
    int B = in_sizes[6];

    int pthreads = 256;
    int pwork = (F > C * 3) ? F : C * 3;
    int pblocks = (pwork + pthreads - 1) / pthreads;
    ppisp_precompute<<<pblocks, pthreads>>>(expo, vig, colp, crf, F, C);

    int threads = 256;
    int n_threads = (B + 3) / 4;
    int blocks = (n_threads + threads - 1) / threads;
    ppisp_main<<<blocks, threads>>>(rgb, coords, cam, frm, pW, pH, out, B);
}

// round 3
// speedup vs baseline: 1.9104x; 1.2514x over previous
#include <cuda_runtime.h>

// PPISP pipeline, two-kernel form with smem-staged frame table.
//
// K1 precompute:
//   per-frame f: fold exp2(exposure[f]) and exp(white balance) into the 3x3
//     color matrix M'. Packed as g_q0[f]={m00,m01,m02,m10},
//     g_q1[f]={m11,m12,m20,m21}, g_m22[f]=m22.
//   per-(camera c, channel j): vignette {v0,v1,p2,p3} and {p4, a, 0.5/c, d*0.5/c}
//     packed as an adjacent float4 pair; the 4 cameras of one channel share a
//     single 128B cache line (so a warp's gather LDG touches exactly 1 line).
//     hb = 0.5*b per (c,j) in one float4 per camera.
//
// K2 main (persistent, 4 points/thread, grid-stride):
//   stage frame table into smem (separate q0/q1/m22 arrays -> chunk column
//   = f mod 8, full bank spread), then per point:
//     2 LDS.128 + 1 LDS.32 (frame) + 7 single-line LDG (camera)
//     + ~45 FMA + 3x(lg2,ex2,tanh) MUFU.
//   sigmoid folded: out = hb*tanh(xp*hc - hd) + hb.
//
// Inputs: 0 expo[F] 1 vig[C,3,5] 2 color[F,8] 3 crf[C,3,4]
//         4 rgb[B,3] 5 coords[B,2] 6 cam[B] 7 frm[B] 8 W 9 H ; out [B,3] f32

#define MAX_F 4096

__device__ float4 g_q0[MAX_F];
__device__ float4 g_q1[MAX_F];
__device__ float  g_m22[MAX_F];
// row j (=channel) base at j*8 float4 = 128B, cameras 0..3 at c*2, c*2+1
__device__ __align__(128) float4 g_cam[3 * 8];
__device__ __align__(128) float4 g_camHb[8];     // {hb0,hb1,hb2,_} per camera

__global__ void ppisp_precompute(const float* __restrict__ expo,
                                 const float* __restrict__ vig,
                                 const float* __restrict__ colp,
                                 const float* __restrict__ crf,
                                 int F, int C)
{
    int t = blockIdx.x * blockDim.x + threadIdx.x;
    if (t < F) {
        float e  = exp2f(expo[t]);
        const float* cp = colp + t * 8;
        float s0 = e * expf(cp[0]);
        float s1 = e;
        float s2 = e * expf(cp[1]);
        float o0 = cp[2], o1 = cp[3], o2 = cp[4];
        float o3 = cp[5], o4 = cp[6], o5 = cp[7];
        g_q0[t] = make_float4((1.0f - o0 - o1) * s0, o0 * s1, o1 * s2, o2 * s0);
        g_q1[t] = make_float4((1.0f - o2 - o3) * s1, o3 * s2, o4 * s0, o5 * s1);
        g_m22[t] = (1.0f - o4 - o5) * s2;
    }
    if (blockIdx.x == 0 && (int)threadIdx.x < C * 3) {
        int c = threadIdx.x / 3;
        int j = threadIdx.x % 3;
        const float* vp = vig + c * 15 + j * 5;
        const float* kp = crf + c * 12 + j * 4;
        float a  = log1pf(expf(kp[0])) + 0.3f;   // accurate softplus (once)
        float b  = log1pf(expf(kp[1])) + 0.3f;
        float cc = log1pf(expf(kp[2])) + 0.1f;
        float d  = kp[3];
        float hc = 0.5f / cc;
        if (c < 4) {
            g_cam[j * 8 + c * 2 + 0] = make_float4(vp[0], vp[1], vp[2], vp[3]);
            g_cam[j * 8 + c * 2 + 1] = make_float4(vp[4], a, hc, d * hc);
            ((float*)&g_camHb[c])[j] = 0.5f * b;
        }
    }
}

__device__ __forceinline__ float fast_lg2(float x) {
    float y; asm("lg2.approx.f32 %0, %1;" : "=f"(y) : "f"(x)); return y;
}
__device__ __forceinline__ float fast_ex2(float x) {
    float y; asm("ex2.approx.f32 %0, %1;" : "=f"(y) : "f"(x)); return y;
}
__device__ __forceinline__ float fast_tanh(float x) {
    float y; asm("tanh.approx.f32 %0, %1;" : "=f"(y) : "f"(x)); return y;
}

__device__ __forceinline__ void process_point(
    float r, float g, float b, float px, float py, int c, int f,
    float invW2, float invH2,
    const float4* __restrict__ s_q0, const float4* __restrict__ s_q1,
    const float* __restrict__ s_m22,
    float* __restrict__ o)
{
    float4 q0 = s_q0[f];
    float4 q1 = s_q1[f];
    float m22 = s_m22[f];

    float u = fmaf(px, invW2, -1.0f);
    float v = fmaf(py, invH2, -1.0f);

    const float4* camb = g_cam + c * 2;
    float rgbv[3] = {r, g, b};
    float t[3], aj[3], hcj[3], hdj[3];
#pragma unroll
    for (int j = 0; j < 3; j++) {
        float4 A = __ldg(camb + j * 8 + 0);
        float4 B = __ldg(camb + j * 8 + 1);
        float du = u - A.x;
        float dv = v - A.y;
        float r2 = fmaf(du, du, dv * dv);
        float gn = fmaf(r2, fmaf(r2, fmaf(r2, B.x, A.w), A.z), 1.0f);
        t[j] = rgbv[j] * gn;
        aj[j] = B.y; hcj[j] = B.z; hdj[j] = B.w;
    }

    float y[3];
    y[0] = fmaf(q0.x, t[0], fmaf(q0.y, t[1], q0.z * t[2]));
    y[1] = fmaf(q0.w, t[0], fmaf(q1.x, t[1], q1.y * t[2]));
    y[2] = fmaf(q1.z, t[0], fmaf(q1.w, t[1], m22  * t[2]));

    float4 HB = __ldg(g_camHb + c);
    float hb[3] = {HB.x, HB.y, HB.z};
#pragma unroll
    for (int j = 0; j < 3; j++) {
        float xp  = fast_ex2(aj[j] * fast_lg2(fmaxf(y[j], 1e-6f)));
        float arg = fmaf(xp, hcj[j], -hdj[j]);
        o[j] = fmaf(hb[j], fast_tanh(arg), hb[j]);
    }
}

__global__ void __launch_bounds__(256, 4)
ppisp_main(const float* __restrict__ rgb,
           const float* __restrict__ coords,
           const int*   __restrict__ cam,
           const int*   __restrict__ frm,
           const int*   __restrict__ pW,
           const int*   __restrict__ pH,
           float* __restrict__ out,
           int B, int F, int Falign)
{
    extern __shared__ float sm[];
    float*  s_m22 = sm;                          // [Falign]
    float4* s_q0  = (float4*)(sm + Falign);      // [F]
    float4* s_q1  = s_q0 + F;                    // [F]

    for (int i = threadIdx.x; i < F; i += blockDim.x) {
        s_m22[i] = g_m22[i];
        s_q0[i]  = g_q0[i];
        s_q1[i]  = g_q1[i];
    }
    __syncthreads();

    float invW2 = 2.0f / (float)__ldg(pW);
    float invH2 = 2.0f / (float)__ldg(pH);

    int nG = (B + 3) >> 2;
    for (int t = blockIdx.x * blockDim.x + threadIdx.x; t < nG;
         t += gridDim.x * blockDim.x) {
        int i0 = t * 4;
        if (i0 + 3 < B) {
            const float4* rgb4 = (const float4*)rgb;
            const float4* pc4  = (const float4*)coords;
            float4 ra = rgb4[3 * t + 0];
            float4 rb = rgb4[3 * t + 1];
            float4 rc = rgb4[3 * t + 2];
            float4 pa = pc4[2 * t + 0];
            float4 pb = pc4[2 * t + 1];
            int4 c4 = ((const int4*)cam)[t];
            int4 f4 = ((const int4*)frm)[t];

            float o[12];
            process_point(ra.x, ra.y, ra.z, pa.x, pa.y, c4.x, f4.x,
                          invW2, invH2, s_q0, s_q1, s_m22, o + 0);
            process_point(ra.w, rb.x, rb.y, pa.z, pa.w, c4.y, f4.y,
                          invW2, invH2, s_q0, s_q1, s_m22, o + 3);
            process_point(rb.z, rb.w, rc.x, pb.x, pb.y, c4.z, f4.z,
                          invW2, invH2, s_q0, s_q1, s_m22, o + 6);
            process_point(rc.y, rc.z, rc.w, pb.z, pb.w, c4.w, f4.w,
                          invW2, invH2, s_q0, s_q1, s_m22, o + 9);

            float4* O = (float4*)out;
            O[3 * t + 0] = make_float4(o[0], o[1], o[2],  o[3]);
            O[3 * t + 1] = make_float4(o[4], o[5], o[6],  o[7]);
            O[3 * t + 2] = make_float4(o[8], o[9], o[10], o[11]);
        } else {
            for (int i = i0; i < B; i++) {
                float o[3];
                process_point(rgb[3 * i], rgb[3 * i + 1], rgb[3 * i + 2],
                              coords[2 * i], coords[2 * i + 1],
                              cam[i], frm[i], invW2, invH2,
                              s_q0, s_q1, s_m22, o);
                out[3 * i + 0] = o[0];
                out[3 * i + 1] = o[1];
                out[3 * i + 2] = o[2];
            }
        }
    }
}

extern "C" void kernel_launch(void* const* d_in, const int* in_sizes, int n_in,
                              void* d_out, int out_size) {
    const float* expo   = (const float*)d_in[0];
    const float* vig    = (const float*)d_in[1];
    const float* colp   = (const float*)d_in[2];
    const float* crf    = (const float*)d_in[3];
    const float* rgb    = (const float*)d_in[4];
    const float* coords = (const float*)d_in[5];
    const int*   cam    = (const int*)d_in[6];
    const int*   frm    = (const int*)d_in[7];
    const int*   pW     = (const int*)d_in[8];
    const int*   pH     = (const int*)d_in[9];
    float* out = (float*)d_out;

    int F = in_sizes[0];
    int C = in_sizes[1] / 15;
    int B = in_sizes[6];
    if (F > MAX_F) F = MAX_F;   // table capacity guard (problem uses F=1000)

    int Falign = (F + 3) & ~3;
    size_t shmem = (size_t)Falign * 4 + (size_t)F * 32;  // m22 + q0 + q1

    // precompute tiny tables
    {
        int pthreads = 256;
        int pwork = (F > C * 3) ? F : C * 3;
        int pblocks = (pwork + pthreads - 1) / pthreads;
        ppisp_precompute<<<pblocks, pthreads>>>(expo, vig, colp, crf, F, C);
    }

    static bool attr_done = false;
    if (!attr_done) {
        cudaFuncSetAttribute(ppisp_main,
                             cudaFuncAttributeMaxDynamicSharedMemorySize,
                             (int)shmem > 49152 ? (int)shmem : 49152);
        attr_done = true;
    }

    int nG = (B + 3) / 4;
    int blocks = (nG + 255) / 256;
    if (blocks > 592) blocks = 592;   // 4 blocks/SM persistent wave
    ppisp_main<<<blocks, 256, shmem>>>(rgb, coords, cam, frm, pW, pH,
                                       out, B, F, Falign);
}

// round 4
// speedup vs baseline: 2.1527x; 1.1268x over previous
#include <cuda_runtime.h>
#include <cuda_fp16.h>

// PPISP pipeline, two-kernel form, mixed-precision packed tables.
//
// K1 precompute:
//   per-frame f: fold exp2(exposure) + exp(WB) into 3x3 matrix M'.
//     g_q[f] = float4 {m00, m11, m22, bits(h2(m01,m02))}   (diag fp32!)
//     g_u[f] = uint2  {bits(h2(m10,m12)), bits(h2(m20,m21))}
//   per-(cam c, channel j):
//     g_Pa[j*4+c] = float4 {h2(v0,v1), h2(p2,p3), h2(p4,d), a(fp32)}
//       (row j = 64B, warp gather touches 1 cache line)
//     g_HC[c] = float4 {h2(hc0,hb0), h2(hc1,hb1), h2(hc2,hb2), 0}
//       hc = 0.5/c_crf, hb = 0.5*b  ->  out = hb + hb*tanh((xp-d)*hc)
//
// K2 main (4 pts/thread, grid-stride, frame table staged in smem):
//   per point: 1 LDS.128 + 1 LDS.64 (frame) + 4 single-line LDG (camera)
//   + ~45 FMA + 3x(lg2,ex2,tanh) MUFU. All streaming as float4/int4.

#define MAX_F 4096

__device__ float4 g_q[MAX_F];
__device__ uint2  g_u[MAX_F];
__device__ __align__(128) float4 g_Pa[3 * 4];   // [j][c]
__device__ __align__(64)  float4 g_HC[4];

__device__ __forceinline__ unsigned int f2h2(float a, float b) {
    __half2 h = __floats2half2_rn(a, b);
    return *reinterpret_cast<unsigned int*>(&h);
}
__device__ __forceinline__ float2 h22f2(unsigned int u) {
    __half2 h = *reinterpret_cast<__half2*>(&u);
    return __half22float2(h);
}

__global__ void ppisp_precompute(const float* __restrict__ expo,
                                 const float* __restrict__ vig,
                                 const float* __restrict__ colp,
                                 const float* __restrict__ crf,
                                 int F, int C)
{
    int t = blockIdx.x * blockDim.x + threadIdx.x;
    if (t < F) {
        float e  = exp2f(expo[t]);
        const float* cp = colp + t * 8;
        float s0 = e * expf(cp[0]);
        float s1 = e;
        float s2 = e * expf(cp[1]);
        float o0 = cp[2], o1 = cp[3], o2 = cp[4];
        float o3 = cp[5], o4 = cp[6], o5 = cp[7];
        float m00 = (1.0f - o0 - o1) * s0, m01 = o0 * s1, m02 = o1 * s2;
        float m10 = o2 * s0, m11 = (1.0f - o2 - o3) * s1, m12 = o3 * s2;
        float m20 = o4 * s0, m21 = o5 * s1, m22 = (1.0f - o4 - o5) * s2;
        float4 q;
        q.x = m00; q.y = m11; q.z = m22;
        q.w = __uint_as_float(f2h2(m01, m02));
        g_q[t] = q;
        g_u[t] = make_uint2(f2h2(m10, m12), f2h2(m20, m21));
    }
    if (blockIdx.x == 0 && (int)threadIdx.x < C * 3 && (int)threadIdx.x < 12) {
        int c = threadIdx.x / 3;
        int j = threadIdx.x % 3;
        const float* vp = vig + c * 15 + j * 5;
        const float* kp = crf + c * 12 + j * 4;
        float a = log1pf(expf(kp[0])) + 0.3f;   // accurate softplus (once)
        float d = kp[3];
        float4 P;
        P.x = __uint_as_float(f2h2(vp[0], vp[1]));
        P.y = __uint_as_float(f2h2(vp[2], vp[3]));
        P.z = __uint_as_float(f2h2(vp[4], d));
        P.w = a;
        g_Pa[j * 4 + c] = P;
    }
    if (blockIdx.x == 0 && (int)threadIdx.x < C && (int)threadIdx.x < 4) {
        int c = threadIdx.x;
        const float* kp = crf + c * 12;
        float4 H; float* Hf = (float*)&H;
#pragma unroll
        for (int j = 0; j < 3; j++) {
            float b  = log1pf(expf(kp[4 * j + 1])) + 0.3f;
            float cc = log1pf(expf(kp[4 * j + 2])) + 0.1f;
            Hf[j] = __uint_as_float(f2h2(0.5f / cc, 0.5f * b));
        }
        Hf[3] = 0.0f;
        g_HC[c] = H;
    }
}

__device__ __forceinline__ float fast_lg2(float x) {
    float y; asm("lg2.approx.f32 %0, %1;" : "=f"(y) : "f"(x)); return y;
}
__device__ __forceinline__ float fast_ex2(float x) {
    float y; asm("ex2.approx.f32 %0, %1;" : "=f"(y) : "f"(x)); return y;
}
__device__ __forceinline__ float fast_tanh(float x) {
    float y; asm("tanh.approx.f32 %0, %1;" : "=f"(y) : "f"(x)); return y;
}

__device__ __forceinline__ void process_point(
    float r, float g, float b, float px, float py, int c, int f,
    float invW2, float invH2,
    const float4* __restrict__ s_q, const uint2* __restrict__ s_u,
    float* __restrict__ o)
{
    float4 q  = s_q[f];
    uint2  uo = s_u[f];
    float2 m0102 = h22f2(__float_as_uint(q.w));
    float2 m1012 = h22f2(uo.x);
    float2 m2021 = h22f2(uo.y);

    float u = fmaf(px, invW2, -1.0f);
    float v = fmaf(py, invH2, -1.0f);

    float rgbv[3] = {r, g, b};
    float t[3], aj[3], dj[3];
#pragma unroll
    for (int j = 0; j < 3; j++) {
        float4 P = __ldg(g_Pa + j * 4 + c);
        float2 v01 = h22f2(__float_as_uint(P.x));
        float2 p23 = h22f2(__float_as_uint(P.y));
        float2 p4d = h22f2(__float_as_uint(P.z));
        float du = u - v01.x;
        float dv = v - v01.y;
        float r2 = fmaf(du, du, dv * dv);
        float gn = fmaf(r2, fmaf(r2, fmaf(r2, p4d.x, p23.y), p23.x), 1.0f);
        t[j] = rgbv[j] * gn;
        aj[j] = P.w;
        dj[j] = p4d.y;
    }

    float y[3];
    y[0] = fmaf(q.x,     t[0], fmaf(m0102.x, t[1], m0102.y * t[2]));
    y[1] = fmaf(m1012.x, t[0], fmaf(q.y,     t[1], m1012.y * t[2]));
    y[2] = fmaf(m2021.x, t[0], fmaf(m2021.y, t[1], q.z     * t[2]));

    float4 HC = __ldg(g_HC + c);
    const float* Hf = (const float*)&HC;
#pragma unroll
    for (int j = 0; j < 3; j++) {
        float2 hcb = h22f2(__float_as_uint(Hf[j]));
        float xp  = fast_ex2(aj[j] * fast_lg2(fmaxf(y[j], 1e-6f)));
        float arg = (xp - dj[j]) * hcb.x;
        o[j] = fmaf(hcb.y, fast_tanh(arg), hcb.y);
    }
}

__global__ void __launch_bounds__(256, 4)
ppisp_main(const float* __restrict__ rgb,
           const float* __restrict__ coords,
           const int*   __restrict__ cam,
           const int*   __restrict__ frm,
           const int*   __restrict__ pW,
           const int*   __restrict__ pH,
           float* __restrict__ out,
           int B, int F)
{
    extern __shared__ float4 smbase[];
    float4* s_q = smbase;                 // [F] 16B records
    uint2*  s_u = (uint2*)(s_q + F);      // [F] 8B records

    for (int i = threadIdx.x; i < F; i += blockDim.x) {
        s_q[i] = g_q[i];
        s_u[i] = g_u[i];
    }
    __syncthreads();

    float invW2 = 2.0f / (float)__ldg(pW);
    float invH2 = 2.0f / (float)__ldg(pH);

    int nG = (B + 3) >> 2;
    for (int t = blockIdx.x * blockDim.x + threadIdx.x; t < nG;
         t += gridDim.x * blockDim.x) {
        int i0 = t * 4;
        if (i0 + 3 < B) {
            const float4* rgb4 = (const float4*)rgb;
            const float4* pc4  = (const float4*)coords;
            float4 ra = rgb4[3 * t + 0];
            float4 rb = rgb4[3 * t + 1];
            float4 rc = rgb4[3 * t + 2];
            float4 pa = pc4[2 * t + 0];
            float4 pb = pc4[2 * t + 1];
            int4 c4 = ((const int4*)cam)[t];
            int4 f4 = ((const int4*)frm)[t];

            float o[12];
            process_point(ra.x, ra.y, ra.z, pa.x, pa.y, c4.x, f4.x,
                          invW2, invH2, s_q, s_u, o + 0);
            process_point(ra.w, rb.x, rb.y, pa.z, pa.w, c4.y, f4.y,
                          invW2, invH2, s_q, s_u, o + 3);
            process_point(rb.z, rb.w, rc.x, pb.x, pb.y, c4.z, f4.z,
                          invW2, invH2, s_q, s_u, o + 6);
            process_point(rc.y, rc.z, rc.w, pb.z, pb.w, c4.w, f4.w,
                          invW2, invH2, s_q, s_u, o + 9);

            float4* O = (float4*)out;
            O[3 * t + 0] = make_float4(o[0], o[1], o[2],  o[3]);
            O[3 * t + 1] = make_float4(o[4], o[5], o[6],  o[7]);
            O[3 * t + 2] = make_float4(o[8], o[9], o[10], o[11]);
        } else {
            for (int i = i0; i < B; i++) {
                float o[3];
                process_point(rgb[3 * i], rgb[3 * i + 1], rgb[3 * i + 2],
                              coords[2 * i], coords[2 * i + 1],
                              cam[i], frm[i], invW2, invH2, s_q, s_u, o);
                out[3 * i + 0] = o[0];
                out[3 * i + 1] = o[1];
                out[3 * i + 2] = o[2];
            }
        }
    }
}

extern "C" void kernel_launch(void* const* d_in, const int* in_sizes, int n_in,
                              void* d_out, int out_size) {
    const float* expo   = (const float*)d_in[0];
    const float* vig    = (const float*)d_in[1];
    const float* colp   = (const float*)d_in[2];
    const float* crf    = (const float*)d_in[3];
    const float* rgb    = (const float*)d_in[4];
    const float* coords = (const float*)d_in[5];
    const int*   cam    = (const int*)d_in[6];
    const int*   frm    = (const int*)d_in[7];
    const int*   pW     = (const int*)d_in[8];
    const int*   pH     = (const int*)d_in[9];
    float* out = (float*)d_out;

    int F = in_sizes[0];
    int C = in_sizes[1] / 15;
    int B = in_sizes[6];
    if (F > MAX_F) F = MAX_F;   // table capacity guard (problem uses F=1000)

    size_t shmem = (size_t)F * (16 + 8);   // s_q + s_u

    {
        int pthreads = 256;
        int pwork = (F > C * 3) ? F : C * 3;
        int pblocks = (pwork + pthreads - 1) / pthreads;
        ppisp_precompute<<<pblocks, pthreads>>>(expo, vig, colp, crf, F, C);
    }

    static bool attr_done = false;
    if (!attr_done) {
        cudaFuncSetAttribute(ppisp_main,
                             cudaFuncAttributeMaxDynamicSharedMemorySize,
                             (int)shmem > 49152 ? (int)shmem : 49152);
        attr_done = true;
    }

    int nG = (B + 3) / 4;
    int blocks = (nG + 255) / 256;
    if (blocks > 592) blocks = 592;   // 4 blocks/SM persistent wave
    ppisp_main<<<blocks, 256, shmem>>>(rgb, coords, cam, frm, pW, pH,
                                       out, B, F);
}

// round 5
// speedup vs baseline: 2.3603x; 1.0965x over previous
#include <cuda_runtime.h>
#include <cuda_fp16.h>

// PPISP pipeline. Round 5: 2 points/thread + higher occupancy (<=42 regs,
// 6 blocks/SM) + ALL tables (frame + camera) staged in shared memory.
//
// Tables (built by K1):
//   g_q[f] = float4 {m00, m11, m22, bits(h2(m01,m02))}   (diag fp32)
//   g_u[f] = uint2  {bits(h2(m10,m12)), bits(h2(m20,m21))}
//   g_Pa[j*4+c] = float4 {h2(v0,v1), h2(p2,p3), h2(p4,d), a(fp32)}
//   g_HC[c]     = float4 {h2(hc0,hb0), h2(hc1,hb1), h2(hc2,hb2), 0}
//     hc = 0.5/c_crf, hb = 0.5*b ; out = hb + hb*tanh((xp-d)*hc)
//
// K2 main: per point 1 LDS.128 + 1 LDS.64 (frame gather) + 4 LDS.128
//   (camera, 4 consecutive quads -> conflict-free) + ~45 FMA + 9 MUFU.
//   Streaming rgb/coords/idcs/out as aligned float2/int2.

#define MAX_F 4096

__device__ float4 g_q[MAX_F];
__device__ uint2  g_u[MAX_F];
__device__ __align__(128) float4 g_Pa[3 * 4];   // [j][c]
__device__ __align__(64)  float4 g_HC[4];

__device__ __forceinline__ unsigned int f2h2(float a, float b) {
    __half2 h = __floats2half2_rn(a, b);
    return *reinterpret_cast<unsigned int*>(&h);
}
__device__ __forceinline__ float2 h22f2(unsigned int u) {
    __half2 h = *reinterpret_cast<__half2*>(&u);
    return __half22float2(h);
}

__global__ void ppisp_precompute(const float* __restrict__ expo,
                                 const float* __restrict__ vig,
                                 const float* __restrict__ colp,
                                 const float* __restrict__ crf,
                                 int F, int C)
{
    int t = blockIdx.x * blockDim.x + threadIdx.x;
    if (t < F) {
        float e  = exp2f(expo[t]);
        const float* cp = colp + t * 8;
        float s0 = e * expf(cp[0]);
        float s1 = e;
        float s2 = e * expf(cp[1]);
        float o0 = cp[2], o1 = cp[3], o2 = cp[4];
        float o3 = cp[5], o4 = cp[6], o5 = cp[7];
        float m00 = (1.0f - o0 - o1) * s0, m01 = o0 * s1, m02 = o1 * s2;
        float m10 = o2 * s0, m11 = (1.0f - o2 - o3) * s1, m12 = o3 * s2;
        float m20 = o4 * s0, m21 = o5 * s1, m22 = (1.0f - o4 - o5) * s2;
        float4 q;
        q.x = m00; q.y = m11; q.z = m22;
        q.w = __uint_as_float(f2h2(m01, m02));
        g_q[t] = q;
        g_u[t] = make_uint2(f2h2(m10, m12), f2h2(m20, m21));
    }
    if (blockIdx.x == 0 && (int)threadIdx.x < C * 3 && (int)threadIdx.x < 12) {
        int c = threadIdx.x / 3;
        int j = threadIdx.x % 3;
        const float* vp = vig + c * 15 + j * 5;
        const float* kp = crf + c * 12 + j * 4;
        float a = log1pf(expf(kp[0])) + 0.3f;   // accurate softplus (once)
        float d = kp[3];
        float4 P;
        P.x = __uint_as_float(f2h2(vp[0], vp[1]));
        P.y = __uint_as_float(f2h2(vp[2], vp[3]));
        P.z = __uint_as_float(f2h2(vp[4], d));
        P.w = a;
        g_Pa[j * 4 + c] = P;
    }
    if (blockIdx.x == 0 && (int)threadIdx.x < C && (int)threadIdx.x < 4) {
        int c = threadIdx.x;
        const float* kp = crf + c * 12;
        float4 H; float* Hf = (float*)&H;
#pragma unroll
        for (int j = 0; j < 3; j++) {
            float b  = log1pf(expf(kp[4 * j + 1])) + 0.3f;
            float cc = log1pf(expf(kp[4 * j + 2])) + 0.1f;
            Hf[j] = __uint_as_float(f2h2(0.5f / cc, 0.5f * b));
        }
        Hf[3] = 0.0f;
        g_HC[c] = H;
    }
}

__device__ __forceinline__ float fast_lg2(float x) {
    float y; asm("lg2.approx.f32 %0, %1;" : "=f"(y) : "f"(x)); return y;
}
__device__ __forceinline__ float fast_ex2(float x) {
    float y; asm("ex2.approx.f32 %0, %1;" : "=f"(y) : "f"(x)); return y;
}
__device__ __forceinline__ float fast_tanh(float x) {
    float y; asm("tanh.approx.f32 %0, %1;" : "=f"(y) : "f"(x)); return y;
}

__device__ __forceinline__ void process_point(
    float r, float g, float b, float px, float py, int c, int f,
    float invW2, float invH2,
    const float4* __restrict__ s_q, const uint2* __restrict__ s_u,
    const float4* __restrict__ s_Pa, const float4* __restrict__ s_HC,
    float* __restrict__ o)
{
    float4 q  = s_q[f];
    uint2  uo = s_u[f];
    float2 m0102 = h22f2(__float_as_uint(q.w));
    float2 m1012 = h22f2(uo.x);
    float2 m2021 = h22f2(uo.y);

    float u = fmaf(px, invW2, -1.0f);
    float v = fmaf(py, invH2, -1.0f);

    float rgbv[3] = {r, g, b};
    float t[3], aj[3], dj[3];
#pragma unroll
    for (int j = 0; j < 3; j++) {
        float4 P = s_Pa[j * 4 + c];
        float2 v01 = h22f2(__float_as_uint(P.x));
        float2 p23 = h22f2(__float_as_uint(P.y));
        float2 p4d = h22f2(__float_as_uint(P.z));
        float du = u - v01.x;
        float dv = v - v01.y;
        float r2 = fmaf(du, du, dv * dv);
        float gn = fmaf(r2, fmaf(r2, fmaf(r2, p4d.x, p23.y), p23.x), 1.0f);
        t[j] = rgbv[j] * gn;
        aj[j] = P.w;
        dj[j] = p4d.y;
    }

    float y[3];
    y[0] = fmaf(q.x,     t[0], fmaf(m0102.x, t[1], m0102.y * t[2]));
    y[1] = fmaf(m1012.x, t[0], fmaf(q.y,     t[1], m1012.y * t[2]));
    y[2] = fmaf(m2021.x, t[0], fmaf(m2021.y, t[1], q.z     * t[2]));

    float4 HC = s_HC[c];
    const float* Hf = (const float*)&HC;
#pragma unroll
    for (int j = 0; j < 3; j++) {
        float2 hcb = h22f2(__float_as_uint(Hf[j]));
        float xp  = fast_ex2(aj[j] * fast_lg2(fmaxf(y[j], 1e-6f)));
        float arg = (xp - dj[j]) * hcb.x;
        o[j] = fmaf(hcb.y, fast_tanh(arg), hcb.y);
    }
}

__global__ void __launch_bounds__(256, 6)
ppisp_main(const float* __restrict__ rgb,
           const float* __restrict__ coords,
           const int*   __restrict__ cam,
           const int*   __restrict__ frm,
           const int*   __restrict__ pW,
           const int*   __restrict__ pH,
           float* __restrict__ out,
           int B, int F)
{
    extern __shared__ float4 smbase[];
    float4* s_q  = smbase;                  // [F] 16B
    float4* s_Pa = s_q + F;                 // [12]
    float4* s_HC = s_Pa + 12;               // [4]
    uint2*  s_u  = (uint2*)(s_HC + 4);      // [F] 8B

    for (int i = threadIdx.x; i < F; i += blockDim.x) {
        s_q[i] = g_q[i];
        s_u[i] = g_u[i];
    }
    if (threadIdx.x < 12) s_Pa[threadIdx.x] = g_Pa[threadIdx.x];
    if (threadIdx.x < 4)  s_HC[threadIdx.x] = g_HC[threadIdx.x];
    __syncthreads();

    float invW2 = 2.0f / (float)__ldg(pW);
    float invH2 = 2.0f / (float)__ldg(pH);

    int nP = (B + 1) >> 1;   // point-pairs
    for (int t = blockIdx.x * blockDim.x + threadIdx.x; t < nP;
         t += gridDim.x * blockDim.x) {
        int i0 = t * 2;
        if (i0 + 1 < B) {
            const float2* rgb2 = (const float2*)rgb;
            const float2* pc2  = (const float2*)coords;
            float2 r01 = rgb2[3 * t + 0];
            float2 r23 = rgb2[3 * t + 1];
            float2 r45 = rgb2[3 * t + 2];
            float2 pa  = pc2[2 * t + 0];
            float2 pb  = pc2[2 * t + 1];
            int2 c2 = ((const int2*)cam)[t];
            int2 f2 = ((const int2*)frm)[t];

            float o[6];
            process_point(r01.x, r01.y, r23.x, pa.x, pa.y, c2.x, f2.x,
                          invW2, invH2, s_q, s_u, s_Pa, s_HC, o + 0);
            process_point(r23.y, r45.x, r45.y, pb.x, pb.y, c2.y, f2.y,
                          invW2, invH2, s_q, s_u, s_Pa, s_HC, o + 3);

            float2* O = (float2*)out;
            O[3 * t + 0] = make_float2(o[0], o[1]);
            O[3 * t + 1] = make_float2(o[2], o[3]);
            O[3 * t + 2] = make_float2(o[4], o[5]);
        } else {
            for (int i = i0; i < B; i++) {
                float o[3];
                process_point(rgb[3 * i], rgb[3 * i + 1], rgb[3 * i + 2],
                              coords[2 * i], coords[2 * i + 1],
                              cam[i], frm[i], invW2, invH2,
                              s_q, s_u, s_Pa, s_HC, o);
                out[3 * i + 0] = o[0];
                out[3 * i + 1] = o[1];
                out[3 * i + 2] = o[2];
            }
        }
    }
}

extern "C" void kernel_launch(void* const* d_in, const int* in_sizes, int n_in,
                              void* d_out, int out_size) {
    const float* expo   = (const float*)d_in[0];
    const float* vig    = (const float*)d_in[1];
    const float* colp   = (const float*)d_in[2];
    const float* crf    = (const float*)d_in[3];
    const float* rgb    = (const float*)d_in[4];
    const float* coords = (const float*)d_in[5];
    const int*   cam    = (const int*)d_in[6];
    const int*   frm    = (const int*)d_in[7];
    const int*   pW     = (const int*)d_in[8];
    const int*   pH     = (const int*)d_in[9];
    float* out = (float*)d_out;

    int F = in_sizes[0];
    int C = in_sizes[1] / 15;
    int B = in_sizes[6];
    if (F > MAX_F) F = MAX_F;   // table capacity guard (problem uses F=1000)

    // s_q[F] + s_Pa[12] + s_HC[4] + s_u[F]
    size_t shmem = (size_t)F * 16 + 16 * 16 + (size_t)F * 8;

    {
        int pthreads = 256;
        int pwork = (F > C * 3) ? F : C * 3;
        int pblocks = (pwork + pthreads - 1) / pthreads;
        ppisp_precompute<<<pblocks, pthreads>>>(expo, vig, colp, crf, F, C);
    }

    static bool attr_done = false;
    if (!attr_done) {
        cudaFuncSetAttribute(ppisp_main,
                             cudaFuncAttributeMaxDynamicSharedMemorySize,
                             (int)shmem > 49152 ? (int)shmem : 49152);
        attr_done = true;
    }

    int nP = (B + 1) / 2;
    int blocks = (nP + 255) / 256;
    int maxb = 148 * 6;
    if (blocks > maxb) blocks = maxb;
    ppisp_main<<<blocks, 256, shmem>>>(rgb, coords, cam, frm, pW, pH,
                                       out, B, F);
}